// round 7
// baseline (speedup 1.0000x reference)
#include <cuda_runtime.h>
#include <cuda_bf16.h>
#include <cstdint>
#include <math.h>

// ---------------- problem constants ----------------
// B=64, T=256, DIN=128, H=256, DZ=8, DX=8
#define ROWS_ 16384              // B*T
#define MZ_OFF 0
#define CHOL_OFF 131072          // 16384*8
#define MX_OFF  33685504         // CHOL_OFF + 8*64*256*256
#define CV_OFF  33816576         // MX_OFF + 16384*8

// ---------------- device scratch (no allocation allowed) ----------------
__device__ __align__(16) float  g_xproj[ROWS_ * 768];   // 50 MB
__device__ __align__(16) float  g_enc[ROWS_ * 256];     // 16 MB
__device__ __align__(16) float  g_op[ROWS_ * 96];       // 6.3 MB
__device__ __align__(16) float  g_wihT[128 * 768];      // W_ih^T  [K=128, N=768]
__device__ __align__(16) float4 g_w4[256 * 256];        // (W_r, W_z, W_n, 0)[j][k] at [k*256+j]
__device__ __align__(16) float  g_wcatT[256 * 96];      // packed head weights [K=256, N=96]
__device__ __align__(16) float  g_bcat[96];

// ---------------- f32x2 helpers ----------------
__device__ __forceinline__ void fma2(unsigned long long& d, unsigned long long a, unsigned long long b) {
    asm("fma.rn.f32x2 %0, %1, %2, %0;" : "+l"(d) : "l"(a), "l"(b));
}
__device__ __forceinline__ unsigned long long dup2(float a) {
    unsigned long long r; asm("mov.b64 %0, {%1, %1};" : "=l"(r) : "f"(a)); return r;
}
__device__ __forceinline__ float2 unpack2(unsigned long long v) {
    float2 r; asm("mov.b64 {%0, %1}, %2;" : "=f"(r.x), "=f"(r.y) : "l"(v)); return r;
}

// ---------------- prep: transposes + packing ----------------
__global__ void __launch_bounds__(256) prep_kernel(
    const float* __restrict__ Wih, const float* __restrict__ Whh,
    const float* __restrict__ Wmz, const float* __restrict__ Wmx,
    const float* __restrict__ Wpz, const float* __restrict__ Wcx,
    const float* __restrict__ bmz, const float* __restrict__ bmx,
    const float* __restrict__ bpz, const float* __restrict__ bcx)
{
    int i = blockIdx.x * 256 + threadIdx.x;
    if (i < 128 * 768) {                       // W_ih^T
        int k = i / 768, n = i % 768;
        g_wihT[i] = Wih[n * 128 + k];
        return;
    }
    int i2 = i - 128 * 768;
    if (i2 < 65536) {                          // GRU weights, k-major, gate-packed
        int k = i2 >> 8, j = i2 & 255;
        g_w4[i2] = make_float4(Whh[j * 256 + k],
                               Whh[(256 + j) * 256 + k],
                               Whh[(512 + j) * 256 + k], 0.f);
        return;
    }
    int i3 = i2 - 65536;
    if (i3 < 24576) {                          // packed head weights^T
        int k = i3 / 96, c = i3 % 96;
        float v;
        if (c < 8)       v = Wmz[c * 256 + k];
        else if (c < 16) v = Wmx[(c - 8) * 256 + k];
        else if (c < 32) v = Wpz[(c - 16) * 256 + k];
        else             v = Wcx[(c - 32) * 256 + k];
        g_wcatT[i3] = v;
        return;
    }
    int i4 = i3 - 24576;
    if (i4 < 96) {
        float v;
        if (i4 < 8)       v = bmz[i4];
        else if (i4 < 16) v = bmx[i4 - 8];
        else if (i4 < 32) v = bpz[i4 - 16];
        else              v = bcx[i4 - 32];
        g_bcat[i4] = v;
    }
}

// ---------------- GEMM: C[M,N] = A[M,K] @ B[K,N] + bias (row-major) ----------------
template <int BM, int BN, int BK, int TM, int TN>
__global__ void __launch_bounds__(256) gemm_kernel(
    const float* __restrict__ A, const float* __restrict__ B,
    const float* __restrict__ bias, float* __restrict__ C,
    int M, int N, int K)
{
    constexpr int TX = BN / TN;
    constexpr int NH = TN / 2;
    __shared__ float Asm[BK][BM];
    __shared__ float Bsm[BK][BN];

    int tid = threadIdx.x;
    int tx = tid % TX, ty = tid / TX;
    int m0 = blockIdx.y * BM, n0 = blockIdx.x * BN;

    unsigned long long acc[TM][NH];
#pragma unroll
    for (int m = 0; m < TM; m++)
#pragma unroll
        for (int i = 0; i < NH; i++) acc[m][i] = 0ull;

    for (int k0 = 0; k0 < K; k0 += BK) {
        for (int i = tid; i < BM * BK / 4; i += 256) {
            int r = i / (BK / 4), c = i % (BK / 4);
            float4 v = *(const float4*)(A + (size_t)(m0 + r) * K + k0 + c * 4);
            Asm[c * 4 + 0][r] = v.x; Asm[c * 4 + 1][r] = v.y;
            Asm[c * 4 + 2][r] = v.z; Asm[c * 4 + 3][r] = v.w;
        }
        for (int i = tid; i < BK * BN / 4; i += 256) {
            int r = i / (BN / 4), c = i % (BN / 4);
            *(float4*)&Bsm[r][c * 4] = *(const float4*)(B + (size_t)(k0 + r) * N + n0 + c * 4);
        }
        __syncthreads();
#pragma unroll
        for (int k = 0; k < BK; k++) {
            float4 av = *(const float4*)&Asm[k][ty * TM];
            unsigned long long am[TM];
            am[0] = dup2(av.x); am[1] = dup2(av.y); am[2] = dup2(av.z); am[3] = dup2(av.w);
            const unsigned long long* bp = (const unsigned long long*)&Bsm[k][tx * TN];
            unsigned long long bv[NH];
#pragma unroll
            for (int i = 0; i < NH; i++) bv[i] = bp[i];
#pragma unroll
            for (int m = 0; m < TM; m++)
#pragma unroll
                for (int i = 0; i < NH; i++) fma2(acc[m][i], am[m], bv[i]);
        }
        __syncthreads();
    }

#pragma unroll
    for (int m = 0; m < TM; m++) {
        int row = m0 + ty * TM + m;
#pragma unroll
        for (int i = 0; i < NH; i++) {
            float2 s = unpack2(acc[m][i]);
            int col = n0 + tx * TN + i * 2;
            C[(size_t)row * N + col]     = s.x + bias[col];
            C[(size_t)row * N + col + 1] = s.y + bias[col + 1];
        }
    }
}

// ---------------- GRU: 32 blocks, 2 batches/block, thread j = hidden unit j ----------------
__global__ void __launch_bounds__(256) gru_kernel(
    const float4* __restrict__ w4, const float* __restrict__ bhh,
    const float* __restrict__ xproj, float* __restrict__ enc)
{
    __shared__ float hs[2][512];   // double buffer, interleaved (batch0, batch1) pairs
    int j = threadIdx.x;
    int b0 = blockIdx.x * 2;

    hs[0][2 * j] = 0.f; hs[0][2 * j + 1] = 0.f;
    float br = bhh[j], bz = bhh[256 + j], bn = bhh[512 + j];
    __syncthreads();

    int cur = 0;
    const float* xpb0 = xproj + (size_t)b0 * 256 * 768;
    for (int t = 0; t < 256; t++) {
        const float* xp0 = xpb0 + (size_t)t * 768;
        const float* xp1 = xp0 + (size_t)256 * 768;

        unsigned long long ar = 0ull, az = 0ull, an = 0ull;
        const unsigned long long* hp = (const unsigned long long*)hs[cur];
        const float4* w4j = w4 + j;
#pragma unroll 8
        for (int k = 0; k < 256; k++) {
            float4 w = w4j[k * 256];           // one coalesced LDG.128 per k
            unsigned long long hv = hp[k];     // broadcast LDS.64 (h[b0],h[b1])
            fma2(ar, dup2(w.x), hv);
            fma2(az, dup2(w.y), hv);
            fma2(an, dup2(w.z), hv);
        }
        float2 sr = unpack2(ar), sz = unpack2(az), sn = unpack2(an);
        float hr0 = sr.x + br, hr1 = sr.y + br;
        float hz0 = sz.x + bz, hz1 = sz.y + bz;
        float hn0 = sn.x + bn, hn1 = sn.y + bn;

        float r0 = 1.f / (1.f + expf(-(xp0[j] + hr0)));
        float z0 = 1.f / (1.f + expf(-(xp0[256 + j] + hz0)));
        float n0 = tanhf(xp0[512 + j] + r0 * hn0);
        float r1 = 1.f / (1.f + expf(-(xp1[j] + hr1)));
        float z1 = 1.f / (1.f + expf(-(xp1[256 + j] + hz1)));
        float n1 = tanhf(xp1[512 + j] + r1 * hn1);

        float hp0 = hs[cur][2 * j], hp1 = hs[cur][2 * j + 1];
        float h0 = (1.f - z0) * n0 + z0 * hp0;
        float h1 = (1.f - z1) * n1 + z1 * hp1;

        int nxt = cur ^ 1;
        hs[nxt][2 * j] = h0; hs[nxt][2 * j + 1] = h1;
        enc[((size_t)b0 * 256 + t) * 256 + j] = h0;
        enc[((size_t)(b0 + 1) * 256 + t) * 256 + j] = h1;
        __syncthreads();
        cur = nxt;
    }
}

// ---------------- small outputs: mean_z, mean_x (anchored), cov_x ----------------
__global__ void __launch_bounds__(512) heads_out_kernel(
    const float* __restrict__ op, float* __restrict__ out)
{
    int idx = blockIdx.x * 512 + threadIdx.x;   // 1,310,720 total
    if (idx < 131072) {                          // mean_z
        int row = idx >> 3, c = idx & 7;
        out[MZ_OFF + idx] = op[row * 96 + c];
    } else if (idx < 262144) {                   // mean_x with t=0 anchoring of dims 0,1
        int i = idx - 131072;
        int row = i >> 3, c = i & 7;
        float v = op[row * 96 + 8 + c];
        if (c < 2) v -= op[((row >> 8) << 8) * 96 + 8 + c];
        out[MX_OFF + i] = v;
    } else {                                     // cov_x
        int i = idx - 262144;
        if (i < 1048576) {
            int row = i >> 6, c = i & 63;
            out[CV_OFF + i] = op[row * 96 + 32 + c];
        }
    }
}

// ---------------- chol_z: [DZ,B,T,T] banded fill ----------------
__global__ void __launch_bounds__(512) chol_kernel(
    const float* __restrict__ op, float* __restrict__ out)
{
    int q = blockIdx.x * 512 + threadIdx.x;      // 8,388,608 float4s
    int j4 = q & 63;
    int rowid = q >> 6;                          // d*16384 + b*256 + i
    int i = rowid & 255;
    int b = (rowid >> 8) & 63;
    int d = rowid >> 14;

    float vv0 = 0.f, vv1 = 0.f, vv2 = 0.f, vv3 = 0.f;
    int jb = j4 << 2;
    int oprow = (b << 8) + i;
    if (i >= jb && i < jb + 4) {                 // diagonal: softplus
        float x = op[oprow * 96 + 16 + d];
        float sp = (x > 15.f) ? x : log1pf(expf(x));
        int p = i - jb;
        if (p == 0) vv0 = sp; else if (p == 1) vv1 = sp; else if (p == 2) vv2 = sp; else vv3 = sp;
    }
    int ip = i + 1;
    if (i < 255 && ip >= jb && ip < jb + 4) {    // superdiagonal
        float offv = op[oprow * 96 + 24 + d];
        int p = ip - jb;
        if (p == 0) vv0 = offv; else if (p == 1) vv1 = offv; else if (p == 2) vv2 = offv; else vv3 = offv;
    }
    *(float4*)(out + CHOL_OFF + ((size_t)q << 2)) = make_float4(vv0, vv1, vv2, vv3);
}

// ---------------- launch ----------------
extern "C" void kernel_launch(void* const* d_in, const int* in_sizes, int n_in,
                              void* d_out, int out_size)
{
    const float* y    = (const float*)d_in[0];
    const float* Wih  = (const float*)d_in[1];
    const float* Whh  = (const float*)d_in[2];
    const float* bih  = (const float*)d_in[3];
    const float* bhh  = (const float*)d_in[4];
    const float* Wmz  = (const float*)d_in[5];
    const float* bmz  = (const float*)d_in[6];
    const float* Wmx  = (const float*)d_in[7];
    const float* bmx  = (const float*)d_in[8];
    const float* Wpz  = (const float*)d_in[9];
    const float* bpz  = (const float*)d_in[10];
    const float* Wcx  = (const float*)d_in[11];
    const float* bcx  = (const float*)d_in[12];
    float* out = (float*)d_out;

    float *xproj, *enc, *op, *wihT, *wcatT, *bcat;
    float4* w4;
    cudaGetSymbolAddress((void**)&xproj, g_xproj);
    cudaGetSymbolAddress((void**)&enc,   g_enc);
    cudaGetSymbolAddress((void**)&op,    g_op);
    cudaGetSymbolAddress((void**)&wihT,  g_wihT);
    cudaGetSymbolAddress((void**)&wcatT, g_wcatT);
    cudaGetSymbolAddress((void**)&bcat,  g_bcat);
    cudaGetSymbolAddress((void**)&w4,    g_w4);

    prep_kernel<<<737, 256>>>(Wih, Whh, Wmz, Wmx, Wpz, Wcx, bmz, bmx, bpz, bcx);

    // x_proj = y @ W_ih^T + b_ih : [16384,768]
    gemm_kernel<64, 64, 32, 4, 4><<<dim3(12, 256), 256>>>(y, wihT, bih, xproj, 16384, 768, 128);

    // GRU recurrence -> enc [16384,256]
    gru_kernel<<<32, 256>>>(w4, bhh, xproj, enc);

    // all heads fused: [16384,96] = enc @ Wcat^T + bcat
    gemm_kernel<64, 96, 32, 4, 6><<<dim3(1, 256), 256>>>(enc, wcatT, bcat, op, 16384, 96, 256);

    heads_out_kernel<<<2560, 512>>>(op, out);
    chol_kernel<<<16384, 512>>>(op, out);
}

// round 13
// speedup vs baseline: 4.5493x; 4.5493x over previous
#include <cuda_runtime.h>
#include <cuda_bf16.h>
#include <cstdint>
#include <math.h>

// ---------------- problem constants ----------------
// B=64, T=256, DIN=128, H=256, DZ=8, DX=8
#define ROWS_ 16384              // B*T
#define MZ_OFF 0
#define CHOL_OFF 131072          // 16384*8
#define MX_OFF  33685504         // CHOL_OFF + 8*64*256*256
#define CV_OFF  33816576         // MX_OFF + 16384*8

// ---------------- device scratch (no allocation allowed) ----------------
__device__ __align__(16) float  g_xproj[ROWS_ * 768];   // 50 MB
__device__ __align__(16) float  g_enc[ROWS_ * 256];     // 16 MB
__device__ __align__(16) float  g_op[ROWS_ * 96];       // 6.3 MB
__device__ __align__(16) float  g_wihT[128 * 768];      // W_ih^T  [K=128, N=768]
__device__ __align__(16) float  g_wcatT[256 * 96];      // packed head weights [K=256, N=96]
__device__ __align__(16) float  g_bcat[96];

// ---------------- f32x2 helpers ----------------
__device__ __forceinline__ void fma2(unsigned long long& d, unsigned long long a, unsigned long long b) {
    asm("fma.rn.f32x2 %0, %1, %2, %0;" : "+l"(d) : "l"(a), "l"(b));
}
__device__ __forceinline__ unsigned long long dup2(float a) {
    unsigned long long r; asm("mov.b64 %0, {%1, %1};" : "=l"(r) : "f"(a)); return r;
}
__device__ __forceinline__ float2 unpack2(unsigned long long v) {
    float2 r; asm("mov.b64 {%0, %1}, %2;" : "=f"(r.x), "=f"(r.y) : "l"(v)); return r;
}
__device__ __forceinline__ unsigned long long add2(unsigned long long a, unsigned long long b) {
    unsigned long long r; asm("add.rn.f32x2 %0, %1, %2;" : "=l"(r) : "l"(a), "l"(b)); return r;
}
__device__ __forceinline__ uint32_t smem_u32(const void* p) {
    uint32_t a; asm("{ .reg .u64 t; cvta.to.shared.u64 t, %1; cvt.u32.u64 %0, t; }" : "=r"(a) : "l"(p));
    return a;
}
__device__ __forceinline__ uint32_t ctarank() {
    uint32_t r; asm("mov.u32 %0, %%cluster_ctarank;" : "=r"(r)); return r;
}
__device__ __forceinline__ void st_cluster_b64(uint32_t addr, uint32_t rank, unsigned long long v) {
    uint32_t ra;
    asm volatile("mapa.shared::cluster.u32 %0, %1, %2;" : "=r"(ra) : "r"(addr), "r"(rank));
    asm volatile("st.shared::cluster.b64 [%0], %1;" :: "r"(ra), "l"(v) : "memory");
}

// ---------------- prep: transposes + packing ----------------
__global__ void __launch_bounds__(256) prep_kernel(
    const float* __restrict__ Wih,
    const float* __restrict__ Wmz, const float* __restrict__ Wmx,
    const float* __restrict__ Wpz, const float* __restrict__ Wcx,
    const float* __restrict__ bmz, const float* __restrict__ bmx,
    const float* __restrict__ bpz, const float* __restrict__ bcx)
{
    int i = blockIdx.x * 256 + threadIdx.x;
    if (i < 128 * 768) {                       // W_ih^T
        int k = i / 768, n = i % 768;
        g_wihT[i] = Wih[n * 128 + k];
        return;
    }
    int i3 = i - 128 * 768;
    if (i3 < 24576) {                          // packed head weights^T
        int k = i3 / 96, c = i3 % 96;
        float v;
        if (c < 8)       v = Wmz[c * 256 + k];
        else if (c < 16) v = Wmx[(c - 8) * 256 + k];
        else if (c < 32) v = Wpz[(c - 16) * 256 + k];
        else             v = Wcx[(c - 32) * 256 + k];
        g_wcatT[i3] = v;
        return;
    }
    int i4 = i3 - 24576;
    if (i4 < 96) {
        float v;
        if (i4 < 8)       v = bmz[i4];
        else if (i4 < 16) v = bmx[i4 - 8];
        else if (i4 < 32) v = bpz[i4 - 16];
        else              v = bcx[i4 - 32];
        g_bcat[i4] = v;
    }
}

// ---------------- GEMM: C[M,N] = A[M,K] @ B[K,N] + bias (row-major) ----------------
template <int BM, int BN, int BK, int TM, int TN>
__global__ void __launch_bounds__(256) gemm_kernel(
    const float* __restrict__ A, const float* __restrict__ B,
    const float* __restrict__ bias, float* __restrict__ C,
    int M, int N, int K)
{
    constexpr int TX = BN / TN;
    constexpr int NH = TN / 2;
    __shared__ float Asm[BK][BM];
    __shared__ float Bsm[BK][BN];

    int tid = threadIdx.x;
    int tx = tid % TX, ty = tid / TX;
    int m0 = blockIdx.y * BM, n0 = blockIdx.x * BN;

    unsigned long long acc[TM][NH];
#pragma unroll
    for (int m = 0; m < TM; m++)
#pragma unroll
        for (int i = 0; i < NH; i++) acc[m][i] = 0ull;

    for (int k0 = 0; k0 < K; k0 += BK) {
        for (int i = tid; i < BM * BK / 4; i += 256) {
            int r = i / (BK / 4), c = i % (BK / 4);
            float4 v = *(const float4*)(A + (size_t)(m0 + r) * K + k0 + c * 4);
            Asm[c * 4 + 0][r] = v.x; Asm[c * 4 + 1][r] = v.y;
            Asm[c * 4 + 2][r] = v.z; Asm[c * 4 + 3][r] = v.w;
        }
        for (int i = tid; i < BK * BN / 4; i += 256) {
            int r = i / (BN / 4), c = i % (BN / 4);
            *(float4*)&Bsm[r][c * 4] = *(const float4*)(B + (size_t)(k0 + r) * N + n0 + c * 4);
        }
        __syncthreads();
#pragma unroll
        for (int k = 0; k < BK; k++) {
            float4 av = *(const float4*)&Asm[k][ty * TM];
            unsigned long long am[TM];
            am[0] = dup2(av.x); am[1] = dup2(av.y); am[2] = dup2(av.z); am[3] = dup2(av.w);
            const unsigned long long* bp = (const unsigned long long*)&Bsm[k][tx * TN];
            unsigned long long bv[NH];
#pragma unroll
            for (int i = 0; i < NH; i++) bv[i] = bp[i];
#pragma unroll
            for (int m = 0; m < TM; m++)
#pragma unroll
                for (int i = 0; i < NH; i++) fma2(acc[m][i], am[m], bv[i]);
        }
        __syncthreads();
    }

#pragma unroll
    for (int m = 0; m < TM; m++) {
        int row = m0 + ty * TM + m;
#pragma unroll
        for (int i = 0; i < NH; i++) {
            float2 s = unpack2(acc[m][i]);
            int col = n0 + tx * TN + i * 2;
            C[(size_t)row * N + col]     = s.x + bias[col];
            C[(size_t)row * N + col + 1] = s.y + bias[col + 1];
        }
    }
}

// ---------------- cluster GRU ----------------
// 32 clusters x 4 CTAs. Cluster c handles batches (2c, 2c+1).
// CTA rank r owns j-slice [64r, 64r+64): weights SMEM-resident (192 KB).
// Dynamic SMEM layout (floats):
//   sW   [3][256][64]  (gate, k, j_local)      = 49152 f = 196608 B
//   hbuf [2][512]      (pairs (b0,b1) per global j, double buffered) = 4096 B
//   gacc ull[192]                               = 1536 B
#define GRU_W_ELEMS  (3*256*64)
#define GRU_SMEM_BYTES (GRU_W_ELEMS*4 + 2*512*4 + 192*8)

__global__ void __cluster_dims__(4, 1, 1) __launch_bounds__(256)
gru_cluster_kernel(const float* __restrict__ Whh, const float* __restrict__ bhh,
                   const float* __restrict__ xproj, float* __restrict__ enc)
{
    extern __shared__ float smem[];
    float* sW = smem;                                  // [3][256][64]
    float* hbuf = smem + GRU_W_ELEMS;                  // [2][512]
    unsigned long long* gacc = (unsigned long long*)(hbuf + 1024); // [192]

    int tid = threadIdx.x;
    uint32_t rank = ctarank();
    int jbase = (int)rank * 64;
    int b0 = (blockIdx.x >> 2) * 2;

    // load weights: sW[g][k][jl] = Whh[(g*256 + jbase + jl)*256 + k]
    for (int idx = tid; idx < GRU_W_ELEMS; idx += 256) {
        int g = idx >> 14;
        int rem = idx & 16383;
        int k = rem >> 6, jl = rem & 63;
        sW[idx] = Whh[(g * 256 + jbase + jl) * 256 + k];
    }
    // init h = 0 (both buffers)
    for (int i = tid; i < 1024; i += 256) hbuf[i] = 0.f;

    // dot-phase thread role
    int g = tid >> 6;          // 0..3 (3 = idle in dot)
    int jl = tid & 63;
    // combine-phase role (tid < 64): global j
    int jg = jbase + tid;
    float br = 0.f, bz = 0.f, bn = 0.f;
    if (tid < 64) { br = bhh[jg]; bz = bhh[256 + jg]; bn = bhh[512 + jg]; }

    uint32_t hbuf_addr = smem_u32(hbuf);

    __syncthreads();
    asm volatile("barrier.cluster.arrive.aligned;" ::: "memory");
    asm volatile("barrier.cluster.wait.aligned;" ::: "memory");

    const float* xpb0 = xproj + (size_t)b0 * 256 * 768;
    const float* xpb1 = xpb0 + (size_t)256 * 768;

    int cur = 0;
    for (int t = 0; t < 256; t++) {
        // prefetch xproj for combine (tid < 64); latency hides under dot
        float xr0, xz0, xn0, xr1, xz1, xn1;
        if (tid < 64) {
            const float* xp0 = xpb0 + (size_t)t * 768;
            const float* xp1 = xpb1 + (size_t)t * 768;
            xr0 = xp0[jg]; xz0 = xp0[256 + jg]; xn0 = xp0[512 + jg];
            xr1 = xp1[jg]; xz1 = xp1[256 + jg]; xn1 = xp1[512 + jg];
        }

        // dot phase: thread (g<3, jl) computes sum_k W[g][jbase+jl][k]*h[k] for both batches
        if (g < 3) {
            const float* wrow = sW + (g << 14) + jl;                     // + k*64
            const unsigned long long* hp = (const unsigned long long*)(hbuf + cur * 512);
            unsigned long long a0 = 0ull, a1 = 0ull;
#pragma unroll 8
            for (int k = 0; k < 256; k += 2) {
                fma2(a0, dup2(wrow[k * 64]), hp[k]);
                fma2(a1, dup2(wrow[(k + 1) * 64]), hp[k + 1]);
            }
            gacc[tid] = add2(a0, a1);
        }
        __syncthreads();

        // combine phase (tid < 64)
        if (tid < 64) {
            float2 sr = unpack2(gacc[tid]);
            float2 sz = unpack2(gacc[64 + tid]);
            float2 sn = unpack2(gacc[128 + tid]);
            float hr0 = sr.x + br, hr1 = sr.y + br;
            float hz0 = sz.x + bz, hz1 = sz.y + bz;
            float hn0 = sn.x + bn, hn1 = sn.y + bn;

            float r0 = 1.f / (1.f + __expf(-(xr0 + hr0)));
            float z0 = 1.f / (1.f + __expf(-(xz0 + hz0)));
            float n0 = tanhf(xn0 + r0 * hn0);
            float r1 = 1.f / (1.f + __expf(-(xr1 + hr1)));
            float z1 = 1.f / (1.f + __expf(-(xz1 + hz1)));
            float n1 = tanhf(xn1 + r1 * hn1);

            // previous h for THIS global unit jg (pair index jg, not tid)
            float hp0 = hbuf[cur * 512 + 2 * jg];
            float hp1 = hbuf[cur * 512 + 2 * jg + 1];
            float h0 = (1.f - z0) * n0 + z0 * hp0;
            float h1 = (1.f - z1) * n1 + z1 * hp1;

            // broadcast new h pair to all 4 CTAs' next buffer
            float2 hv = make_float2(h0, h1);
            unsigned long long hvq = *(unsigned long long*)&hv;
            uint32_t dst = hbuf_addr + (((cur ^ 1) * 512 + 2 * jg) << 2);
            st_cluster_b64(dst, 0, hvq);
            st_cluster_b64(dst, 1, hvq);
            st_cluster_b64(dst, 2, hvq);
            st_cluster_b64(dst, 3, hvq);

            enc[((size_t)b0 * 256 + t) * 256 + jg] = h0;
            enc[((size_t)(b0 + 1) * 256 + t) * 256 + jg] = h1;
        }

        // one cluster barrier per step: orders peer h-writes (release/acquire)
        asm volatile("barrier.cluster.arrive.aligned;" ::: "memory");
        asm volatile("barrier.cluster.wait.aligned;" ::: "memory");
        cur ^= 1;
    }
}

// ---------------- small outputs: mean_z, mean_x (anchored), cov_x ----------------
__global__ void __launch_bounds__(512) heads_out_kernel(
    const float* __restrict__ op, float* __restrict__ out)
{
    int idx = blockIdx.x * 512 + threadIdx.x;   // 1,310,720 total
    if (idx < 131072) {                          // mean_z
        int row = idx >> 3, c = idx & 7;
        out[MZ_OFF + idx] = op[row * 96 + c];
    } else if (idx < 262144) {                   // mean_x with t=0 anchoring of dims 0,1
        int i = idx - 131072;
        int row = i >> 3, c = i & 7;
        float v = op[row * 96 + 8 + c];
        if (c < 2) v -= op[((row >> 8) << 8) * 96 + 8 + c];
        out[MX_OFF + i] = v;
    } else {                                     // cov_x
        int i = idx - 262144;
        if (i < 1048576) {
            int row = i >> 6, c = i & 63;
            out[CV_OFF + i] = op[row * 96 + 32 + c];
        }
    }
}

// ---------------- chol_z: [DZ,B,T,T] banded fill ----------------
__global__ void __launch_bounds__(512) chol_kernel(
    const float* __restrict__ op, float* __restrict__ out)
{
    int q = blockIdx.x * 512 + threadIdx.x;      // 8,388,608 float4s
    int j4 = q & 63;
    int rowid = q >> 6;                          // d*16384 + b*256 + i
    int i = rowid & 255;
    int b = (rowid >> 8) & 63;
    int d = rowid >> 14;

    float vv0 = 0.f, vv1 = 0.f, vv2 = 0.f, vv3 = 0.f;
    int jb = j4 << 2;
    int oprow = (b << 8) + i;
    if (i >= jb && i < jb + 4) {                 // diagonal: softplus
        float x = op[oprow * 96 + 16 + d];
        float sp = (x > 15.f) ? x : log1pf(expf(x));
        int p = i - jb;
        if (p == 0) vv0 = sp; else if (p == 1) vv1 = sp; else if (p == 2) vv2 = sp; else vv3 = sp;
    }
    int ip = i + 1;
    if (i < 255 && ip >= jb && ip < jb + 4) {    // superdiagonal
        float offv = op[oprow * 96 + 24 + d];
        int p = ip - jb;
        if (p == 0) vv0 = offv; else if (p == 1) vv1 = offv; else if (p == 2) vv2 = offv; else vv3 = offv;
    }
    *(float4*)(out + CHOL_OFF + ((size_t)q << 2)) = make_float4(vv0, vv1, vv2, vv3);
}

// ---------------- launch ----------------
extern "C" void kernel_launch(void* const* d_in, const int* in_sizes, int n_in,
                              void* d_out, int out_size)
{
    const float* y    = (const float*)d_in[0];
    const float* Wih  = (const float*)d_in[1];
    const float* Whh  = (const float*)d_in[2];
    const float* bih  = (const float*)d_in[3];
    const float* bhh  = (const float*)d_in[4];
    const float* Wmz  = (const float*)d_in[5];
    const float* bmz  = (const float*)d_in[6];
    const float* Wmx  = (const float*)d_in[7];
    const float* bmx  = (const float*)d_in[8];
    const float* Wpz  = (const float*)d_in[9];
    const float* bpz  = (const float*)d_in[10];
    const float* Wcx  = (const float*)d_in[11];
    const float* bcx  = (const float*)d_in[12];
    float* out = (float*)d_out;

    float *xproj, *enc, *op, *wihT, *wcatT, *bcat;
    cudaGetSymbolAddress((void**)&xproj, g_xproj);
    cudaGetSymbolAddress((void**)&enc,   g_enc);
    cudaGetSymbolAddress((void**)&op,    g_op);
    cudaGetSymbolAddress((void**)&wihT,  g_wihT);
    cudaGetSymbolAddress((void**)&wcatT, g_wcatT);
    cudaGetSymbolAddress((void**)&bcat,  g_bcat);

    cudaFuncSetAttribute(gru_cluster_kernel,
                         cudaFuncAttributeMaxDynamicSharedMemorySize, GRU_SMEM_BYTES);

    prep_kernel<<<737, 256>>>(Wih, Wmz, Wmx, Wpz, Wcx, bmz, bmx, bpz, bcx);

    // x_proj = y @ W_ih^T + b_ih : [16384,768]
    gemm_kernel<64, 64, 32, 4, 4><<<dim3(12, 256), 256>>>(y, wihT, bih, xproj, 16384, 768, 128);

    // GRU recurrence -> enc [16384,256]
    gru_cluster_kernel<<<128, 256, GRU_SMEM_BYTES>>>(Whh, bhh, xproj, enc);

    // all heads fused: [16384,96] = enc @ Wcat^T + bcat
    gemm_kernel<64, 96, 32, 4, 6><<<dim3(1, 256), 256>>>(enc, wcatT, bcat, op, 16384, 96, 256);

    heads_out_kernel<<<2560, 512>>>(op, out);
    chol_kernel<<<16384, 512>>>(op, out);
}

// round 14
// speedup vs baseline: 5.5833x; 1.2273x over previous
#include <cuda_runtime.h>
#include <cuda_bf16.h>
#include <cstdint>
#include <math.h>

// ---------------- problem constants ----------------
// B=64, T=256, DIN=128, H=256, DZ=8, DX=8
#define ROWS_ 16384              // B*T
#define MZ_OFF 0
#define CHOL_OFF 131072          // 16384*8
#define MX_OFF  33685504         // CHOL_OFF + 8*64*256*256
#define CV_OFF  33816576         // MX_OFF + 16384*8

// ---------------- device scratch (no allocation allowed) ----------------
__device__ __align__(16) float  g_xproj[ROWS_ * 768];   // 50 MB
__device__ __align__(16) float  g_enc[ROWS_ * 256];     // 16 MB
__device__ __align__(16) float  g_op[ROWS_ * 96];       // 6.3 MB
__device__ __align__(16) float  g_wihT[128 * 768];      // W_ih^T  [K=128, N=768]
__device__ __align__(16) float  g_wcatT[256 * 96];      // packed head weights [K=256, N=96]
__device__ __align__(16) float  g_bcat[96];

// ---------------- f32x2 helpers ----------------
__device__ __forceinline__ void fma2(unsigned long long& d, unsigned long long a, unsigned long long b) {
    asm("fma.rn.f32x2 %0, %1, %2, %0;" : "+l"(d) : "l"(a), "l"(b));
}
__device__ __forceinline__ unsigned long long dup2(float a) {
    unsigned long long r; asm("mov.b64 %0, {%1, %1};" : "=l"(r) : "f"(a)); return r;
}
__device__ __forceinline__ float2 unpack2(unsigned long long v) {
    float2 r; asm("mov.b64 {%0, %1}, %2;" : "=f"(r.x), "=f"(r.y) : "l"(v)); return r;
}
__device__ __forceinline__ unsigned long long add2(unsigned long long a, unsigned long long b) {
    unsigned long long r; asm("add.rn.f32x2 %0, %1, %2;" : "=l"(r) : "l"(a), "l"(b)); return r;
}
__device__ __forceinline__ uint32_t smem_u32(const void* p) {
    uint32_t a; asm("{ .reg .u64 t; cvta.to.shared.u64 t, %1; cvt.u32.u64 %0, t; }" : "=r"(a) : "l"(p));
    return a;
}
__device__ __forceinline__ uint32_t ctarank() {
    uint32_t r; asm("mov.u32 %0, %%cluster_ctarank;" : "=r"(r)); return r;
}
__device__ __forceinline__ void st_cluster_b64(uint32_t addr, uint32_t rank, unsigned long long v) {
    uint32_t ra;
    asm volatile("mapa.shared::cluster.u32 %0, %1, %2;" : "=r"(ra) : "r"(addr), "r"(rank));
    asm volatile("st.shared::cluster.b64 [%0], %1;" :: "r"(ra), "l"(v) : "memory");
}

// ---------------- prep: transposes + packing ----------------
__global__ void __launch_bounds__(256) prep_kernel(
    const float* __restrict__ Wih,
    const float* __restrict__ Wmz, const float* __restrict__ Wmx,
    const float* __restrict__ Wpz, const float* __restrict__ Wcx,
    const float* __restrict__ bmz, const float* __restrict__ bmx,
    const float* __restrict__ bpz, const float* __restrict__ bcx)
{
    int i = blockIdx.x * 256 + threadIdx.x;
    if (i < 128 * 768) {                       // W_ih^T
        int k = i / 768, n = i % 768;
        g_wihT[i] = Wih[n * 128 + k];
        return;
    }
    int i3 = i - 128 * 768;
    if (i3 < 24576) {                          // packed head weights^T
        int k = i3 / 96, c = i3 % 96;
        float v;
        if (c < 8)       v = Wmz[c * 256 + k];
        else if (c < 16) v = Wmx[(c - 8) * 256 + k];
        else if (c < 32) v = Wpz[(c - 16) * 256 + k];
        else             v = Wcx[(c - 32) * 256 + k];
        g_wcatT[i3] = v;
        return;
    }
    int i4 = i3 - 24576;
    if (i4 < 96) {
        float v;
        if (i4 < 8)       v = bmz[i4];
        else if (i4 < 16) v = bmx[i4 - 8];
        else if (i4 < 32) v = bpz[i4 - 16];
        else              v = bcx[i4 - 32];
        g_bcat[i4] = v;
    }
}

// ---------------- GEMM: C[M,N] = A[M,K] @ B[K,N] + bias (row-major) ----------------
template <int BM, int BN, int BK, int TM, int TN>
__global__ void __launch_bounds__(256) gemm_kernel(
    const float* __restrict__ A, const float* __restrict__ B,
    const float* __restrict__ bias, float* __restrict__ C,
    int M, int N, int K)
{
    constexpr int TX = BN / TN;
    constexpr int NH = TN / 2;
    __shared__ float Asm[BK][BM];
    __shared__ float Bsm[BK][BN];

    int tid = threadIdx.x;
    int tx = tid % TX, ty = tid / TX;
    int m0 = blockIdx.y * BM, n0 = blockIdx.x * BN;

    unsigned long long acc[TM][NH];
#pragma unroll
    for (int m = 0; m < TM; m++)
#pragma unroll
        for (int i = 0; i < NH; i++) acc[m][i] = 0ull;

    for (int k0 = 0; k0 < K; k0 += BK) {
        for (int i = tid; i < BM * BK / 4; i += 256) {
            int r = i / (BK / 4), c = i % (BK / 4);
            float4 v = *(const float4*)(A + (size_t)(m0 + r) * K + k0 + c * 4);
            Asm[c * 4 + 0][r] = v.x; Asm[c * 4 + 1][r] = v.y;
            Asm[c * 4 + 2][r] = v.z; Asm[c * 4 + 3][r] = v.w;
        }
        for (int i = tid; i < BK * BN / 4; i += 256) {
            int r = i / (BN / 4), c = i % (BN / 4);
            *(float4*)&Bsm[r][c * 4] = *(const float4*)(B + (size_t)(k0 + r) * N + n0 + c * 4);
        }
        __syncthreads();
#pragma unroll
        for (int k = 0; k < BK; k++) {
            float4 av = *(const float4*)&Asm[k][ty * TM];
            unsigned long long am[TM];
            am[0] = dup2(av.x); am[1] = dup2(av.y); am[2] = dup2(av.z); am[3] = dup2(av.w);
            const unsigned long long* bp = (const unsigned long long*)&Bsm[k][tx * TN];
            unsigned long long bv[NH];
#pragma unroll
            for (int i = 0; i < NH; i++) bv[i] = bp[i];
#pragma unroll
            for (int m = 0; m < TM; m++)
#pragma unroll
                for (int i = 0; i < NH; i++) fma2(acc[m][i], am[m], bv[i]);
        }
        __syncthreads();
    }

#pragma unroll
    for (int m = 0; m < TM; m++) {
        int row = m0 + ty * TM + m;
#pragma unroll
        for (int i = 0; i < NH; i++) {
            float2 s = unpack2(acc[m][i]);
            int col = n0 + tx * TN + i * 2;
            C[(size_t)row * N + col]     = s.x + bias[col];
            C[(size_t)row * N + col + 1] = s.y + bias[col + 1];
        }
    }
}

// ---------------- cluster GRU ----------------
// 32 clusters x 4 CTAs, 192 threads/CTA. Cluster c handles batches (2c, 2c+1).
// CTA rank r owns j-slice [64r, 64r+64): weights SMEM-resident.
// Weight layout: sW[(g*64 + jl) * 260 + k]  (k-contiguous row, padded 256->260
// so LDS.128 phases are bank-conflict-free: bank offset = jl*4 mod 32).
// hbuf: [2][512] floats = pairs (b0,b1) per global j, double buffered.
// gacc: ull[192] dot results.
#define GRU_ROW    260
#define GRU_W_FLOATS (3*64*GRU_ROW)                     // 49920
#define GRU_SMEM_BYTES (GRU_W_FLOATS*4 + 2*512*4 + 192*8) // 205312

__global__ void __cluster_dims__(4, 1, 1) __launch_bounds__(192)
gru_cluster_kernel(const float* __restrict__ Whh, const float* __restrict__ bhh,
                   const float* __restrict__ xproj, float* __restrict__ enc)
{
    extern __shared__ float smem[];
    float* sW = smem;                                   // [3*64][260]
    float* hbuf = smem + GRU_W_FLOATS;                  // [2][512]
    unsigned long long* gacc = (unsigned long long*)(hbuf + 1024); // [192]

    int tid = threadIdx.x;
    uint32_t rank = ctarank();
    int jbase = (int)rank * 64;
    int b0 = (blockIdx.x >> 2) * 2;

    // load weights: sW[(g*64+jl)*260 + k] = Whh[(g*256 + jbase + jl)*256 + k]
    for (int idx = tid; idx < 3 * 64 * 256; idx += 192) {
        int g = idx >> 14;             // 16384 per gate
        int rem = idx & 16383;
        int jl = rem >> 8, k = rem & 255;
        sW[(g * 64 + jl) * GRU_ROW + k] = Whh[(g * 256 + jbase + jl) * 256 + k];
    }
    // init h = 0 (both buffers)
    for (int i = tid; i < 1024; i += 192) hbuf[i] = 0.f;

    // dot-phase role: thread (g = tid/64 in 0..2, jl = tid%64)
    int g = tid >> 6;
    int jl = tid & 63;
    // combine-phase role (tid < 64): global j
    int jg = jbase + tid;
    float br = 0.f, bz = 0.f, bn = 0.f;
    if (tid < 64) { br = bhh[jg]; bz = bhh[256 + jg]; bn = bhh[512 + jg]; }

    uint32_t hbuf_addr = smem_u32(hbuf);
    const float4* wrow4 = (const float4*)(sW + (g * 64 + jl) * GRU_ROW);

    __syncthreads();
    asm volatile("barrier.cluster.arrive.aligned;" ::: "memory");
    asm volatile("barrier.cluster.wait.aligned;" ::: "memory");

    const float* xpb0 = xproj + (size_t)b0 * 256 * 768;
    const float* xpb1 = xpb0 + (size_t)256 * 768;

    int cur = 0;
    for (int t = 0; t < 256; t++) {
        // prefetch xproj for combine (tid < 64); latency hides under dot
        float xr0, xz0, xn0, xr1, xz1, xn1;
        if (tid < 64) {
            const float* xp0 = xpb0 + (size_t)t * 768;
            const float* xp1 = xpb1 + (size_t)t * 768;
            xr0 = xp0[jg]; xz0 = xp0[256 + jg]; xn0 = xp0[512 + jg];
            xr1 = xp1[jg]; xz1 = xp1[256 + jg]; xn1 = xp1[512 + jg];
        }

        // dot phase: thread (g, jl) computes sum_k W[g][jbase+jl][k]*h[k] (both batches)
        {
            const float4* hp4 = (const float4*)(hbuf + cur * 512);  // pair-quads
            unsigned long long a0 = 0ull, a1 = 0ull, a2 = 0ull, a3 = 0ull;
#pragma unroll 8
            for (int i = 0; i < 64; i++) {                 // 4 k's per iter
                float4 w = wrow4[i];                        // LDS.128, conflict-free
                float4 hA = hp4[2 * i];                     // pairs k=4i, 4i+1 (broadcast)
                float4 hB = hp4[2 * i + 1];                 // pairs k=4i+2, 4i+3
                unsigned long long hA0 = *(unsigned long long*)&hA.x;
                unsigned long long hA1 = *(unsigned long long*)&hA.z;
                unsigned long long hB0 = *(unsigned long long*)&hB.x;
                unsigned long long hB1 = *(unsigned long long*)&hB.z;
                fma2(a0, dup2(w.x), hA0);
                fma2(a1, dup2(w.y), hA1);
                fma2(a2, dup2(w.z), hB0);
                fma2(a3, dup2(w.w), hB1);
            }
            gacc[tid] = add2(add2(a0, a2), add2(a1, a3));
        }
        __syncthreads();

        // combine phase (tid < 64)
        if (tid < 64) {
            float2 sr = unpack2(gacc[tid]);
            float2 sz = unpack2(gacc[64 + tid]);
            float2 sn = unpack2(gacc[128 + tid]);
            float hr0 = sr.x + br, hr1 = sr.y + br;
            float hz0 = sz.x + bz, hz1 = sz.y + bz;
            float hn0 = sn.x + bn, hn1 = sn.y + bn;

            float r0 = 1.f / (1.f + __expf(-(xr0 + hr0)));
            float z0 = 1.f / (1.f + __expf(-(xz0 + hz0)));
            float n0 = tanhf(xn0 + r0 * hn0);
            float r1 = 1.f / (1.f + __expf(-(xr1 + hr1)));
            float z1 = 1.f / (1.f + __expf(-(xz1 + hz1)));
            float n1 = tanhf(xn1 + r1 * hn1);

            // previous h for THIS global unit jg
            float hp0 = hbuf[cur * 512 + 2 * jg];
            float hp1 = hbuf[cur * 512 + 2 * jg + 1];
            float h0 = (1.f - z0) * n0 + z0 * hp0;
            float h1 = (1.f - z1) * n1 + z1 * hp1;

            // broadcast new h pair to all 4 CTAs' next buffer
            float2 hv = make_float2(h0, h1);
            unsigned long long hvq = *(unsigned long long*)&hv;
            uint32_t dst = hbuf_addr + (((cur ^ 1) * 512 + 2 * jg) << 2);
            st_cluster_b64(dst, 0, hvq);
            st_cluster_b64(dst, 1, hvq);
            st_cluster_b64(dst, 2, hvq);
            st_cluster_b64(dst, 3, hvq);

            enc[((size_t)b0 * 256 + t) * 256 + jg] = h0;
            enc[((size_t)(b0 + 1) * 256 + t) * 256 + jg] = h1;
        }

        // one cluster barrier per step: orders peer h-writes (release/acquire)
        asm volatile("barrier.cluster.arrive.aligned;" ::: "memory");
        asm volatile("barrier.cluster.wait.aligned;" ::: "memory");
        cur ^= 1;
    }
}

// ---------------- small outputs: mean_z, mean_x (anchored), cov_x ----------------
__global__ void __launch_bounds__(512) heads_out_kernel(
    const float* __restrict__ op, float* __restrict__ out)
{
    int idx = blockIdx.x * 512 + threadIdx.x;   // 1,310,720 total
    if (idx < 131072) {                          // mean_z
        int row = idx >> 3, c = idx & 7;
        out[MZ_OFF + idx] = op[row * 96 + c];
    } else if (idx < 262144) {                   // mean_x with t=0 anchoring of dims 0,1
        int i = idx - 131072;
        int row = i >> 3, c = i & 7;
        float v = op[row * 96 + 8 + c];
        if (c < 2) v -= op[((row >> 8) << 8) * 96 + 8 + c];
        out[MX_OFF + i] = v;
    } else {                                     // cov_x
        int i = idx - 262144;
        if (i < 1048576) {
            int row = i >> 6, c = i & 63;
            out[CV_OFF + i] = op[row * 96 + 32 + c];
        }
    }
}

// ---------------- chol_z: [DZ,B,T,T] banded fill ----------------
__global__ void __launch_bounds__(512) chol_kernel(
    const float* __restrict__ op, float* __restrict__ out)
{
    int q = blockIdx.x * 512 + threadIdx.x;      // 8,388,608 float4s
    int j4 = q & 63;
    int rowid = q >> 6;                          // d*16384 + b*256 + i
    int i = rowid & 255;
    int b = (rowid >> 8) & 63;
    int d = rowid >> 14;

    float vv0 = 0.f, vv1 = 0.f, vv2 = 0.f, vv3 = 0.f;
    int jb = j4 << 2;
    int oprow = (b << 8) + i;
    if (i >= jb && i < jb + 4) {                 // diagonal: softplus
        float x = op[oprow * 96 + 16 + d];
        float sp = (x > 15.f) ? x : log1pf(expf(x));
        int p = i - jb;
        if (p == 0) vv0 = sp; else if (p == 1) vv1 = sp; else if (p == 2) vv2 = sp; else vv3 = sp;
    }
    int ip = i + 1;
    if (i < 255 && ip >= jb && ip < jb + 4) {    // superdiagonal
        float offv = op[oprow * 96 + 24 + d];
        int p = ip - jb;
        if (p == 0) vv0 = offv; else if (p == 1) vv1 = offv; else if (p == 2) vv2 = offv; else vv3 = offv;
    }
    *(float4*)(out + CHOL_OFF + ((size_t)q << 2)) = make_float4(vv0, vv1, vv2, vv3);
}

// ---------------- launch ----------------
extern "C" void kernel_launch(void* const* d_in, const int* in_sizes, int n_in,
                              void* d_out, int out_size)
{
    const float* y    = (const float*)d_in[0];
    const float* Wih  = (const float*)d_in[1];
    const float* Whh  = (const float*)d_in[2];
    const float* bih  = (const float*)d_in[3];
    const float* bhh  = (const float*)d_in[4];
    const float* Wmz  = (const float*)d_in[5];
    const float* bmz  = (const float*)d_in[6];
    const float* Wmx  = (const float*)d_in[7];
    const float* bmx  = (const float*)d_in[8];
    const float* Wpz  = (const float*)d_in[9];
    const float* bpz  = (const float*)d_in[10];
    const float* Wcx  = (const float*)d_in[11];
    const float* bcx  = (const float*)d_in[12];
    float* out = (float*)d_out;

    float *xproj, *enc, *op, *wihT, *wcatT, *bcat;
    cudaGetSymbolAddress((void**)&xproj, g_xproj);
    cudaGetSymbolAddress((void**)&enc,   g_enc);
    cudaGetSymbolAddress((void**)&op,    g_op);
    cudaGetSymbolAddress((void**)&wihT,  g_wihT);
    cudaGetSymbolAddress((void**)&wcatT, g_wcatT);
    cudaGetSymbolAddress((void**)&bcat,  g_bcat);

    cudaFuncSetAttribute(gru_cluster_kernel,
                         cudaFuncAttributeMaxDynamicSharedMemorySize, GRU_SMEM_BYTES);

    prep_kernel<<<737, 256>>>(Wih, Wmz, Wmx, Wpz, Wcx, bmz, bmx, bpz, bcx);

    // x_proj = y @ W_ih^T + b_ih : [16384,768]
    gemm_kernel<64, 64, 32, 4, 4><<<dim3(12, 256), 256>>>(y, wihT, bih, xproj, 16384, 768, 128);

    // GRU recurrence -> enc [16384,256]
    gru_cluster_kernel<<<128, 192, GRU_SMEM_BYTES>>>(Whh, bhh, xproj, enc);

    // all heads fused: [16384,96] = enc @ Wcat^T + bcat
    gemm_kernel<64, 96, 32, 4, 6><<<dim3(1, 256), 256>>>(enc, wcatT, bcat, op, 16384, 96, 256);

    heads_out_kernel<<<2560, 512>>>(op, out);
    chol_kernel<<<16384, 512>>>(op, out);
}